// round 8
// baseline (speedup 1.0000x reference)
#include <cuda_runtime.h>

// DCT compression: per 8x8 block 2D DCT (cos basis with PI=3.1415), diagonal
// norm, zigzag channel scatter, 1/Q quant scale. Single fused kernel.
//
// R8: keep R7's FFMA-immediate constexpr-table structure (no smem, no LDS).
// Restructure compute to row-streaming: per loaded row, x-DCT the row then
// accumulate into the 64 coef accumulators (multipliers all immediates).
// Kills the 64-reg blk array -> ~78 live regs -> 6 CTAs/SM for latency hiding.
//
// Input : x (32, 3, 512, 512) f32
// Output: (32, 192, 64, 64) f32, out[b, c*64 + z(a,u), hb, wb]

// ---- constexpr math (compile-time only) ----
__host__ __device__ constexpr double cc_cos(double x) {
    const double TWO_PI = 6.283185307179586476925286766559;
    const double PI_D   = 3.14159265358979323846;
    while (x >  PI_D) x -= TWO_PI;
    while (x < -PI_D) x += TWO_PI;
    double x2 = x * x, t = 1.0, s = 1.0;
    for (int n = 1; n <= 16; ++n) { t *= -x2 / ((2.0 * n - 1.0) * (2.0 * n)); s += t; }
    return s;
}

// Mirrors the module: arg = f32((f+0.5)*3.1415f) * f32(j*0.125f), cos of that.
__host__ __device__ constexpr float cc_cm(int f, int j) {
    float ap = (float)(f + 0.5f) * 3.1415f;
    float bj = (float)j * 0.125f;
    return (float)cc_cos((double)(ap * bj));
}

// Module's zigzag() p[y][x], closed form.
__host__ __device__ constexpr int zz_p(int y, int x) {
    int s = x + y;
    if (s < 8) {
        int t = (s + 1) * (s + 2) / 2;
        return (s & 1) ? (t - y - 1) : (t - x - 1);
    }
    int yy = 7 - y, xx = 7 - x;
    int s2 = xx + yy;
    int t = (s2 + 1) * (s2 + 2) / 2;
    return 63 - ((s2 & 1) ? (t - yy - 1) : (t - xx - 1));
}

struct Tabs {
    float cm[8][8];     // cos basis
    float scl[2][8][8]; // [luma?0:1][a][u] = norm(a,u)/Q[ch]
    int   ch[8][8];     // zigzag channel for (a,u)
};

__host__ __device__ constexpr Tabs make_tabs() {
    constexpr float TLQ[64] = {
        16,11,10,16,24,40,51,61, 12,12,14,19,26,58,60,55,
        14,13,16,24,40,57,69,56, 14,17,22,29,51,87,80,62,
        18,22,37,56,68,109,103,77, 24,35,55,64,81,104,113,92,
        49,64,78,87,103,121,120,101, 72,92,95,98,112,100,103,99};
    constexpr float CQQ[64] = {
        17,18,24,47,99,99,99,99, 18,21,26,66,99,99,99,99,
        24,26,56,99,99,99,99,99, 47,66,99,99,99,99,99,99,
        99,99,99,99,99,99,99,99, 99,99,99,99,99,99,99,99,
        99,99,99,99,99,99,99,99, 99,99,99,99,99,99,99,99};
    Tabs t{};
    for (int f = 0; f < 8; ++f)
        for (int j = 0; j < 8; ++j)
            t.cm[f][j] = cc_cm(f, j);
    for (int a = 0; a < 8; ++a)
        for (int u = 0; u < 8; ++u) {
            int ch = zz_p(u, a);                // z = pattern.T
            t.ch[a][u] = ch;
            float nrm = ((a == 0) || (u == 0)) ? 0.17677669529663687f : 0.25f;
            t.scl[0][a][u] = nrm / TLQ[ch];
            t.scl[1][a][u] = nrm / CQQ[ch];
        }
    return t;
}

template<int LC>
__device__ __forceinline__ void dct_body(const float* __restrict__ src,
                                         float* __restrict__ dst) {
    constexpr Tabs T = make_tabs();   // fully folded to immediates

    float coef[8][8];                 // coef[a][u] accumulators (64 regs)

#pragma unroll
    for (int y = 0; y < 8; ++y) {
        float4 p0 = __ldg((const float4*)(src + (long)y * 512));
        float4 p1 = __ldg((const float4*)(src + (long)y * 512 + 4));
        float row[8] = {p0.x, p0.y, p0.z, p0.w, p1.x, p1.y, p1.z, p1.w};

#pragma unroll
        for (int u = 0; u < 8; ++u) {
            // x-DCT of this row: s = dot(row, cm[u][*]); cm[u][0]==1 folds
            float s = row[0] * T.cm[u][0];
#pragma unroll
            for (int xx = 1; xx < 8; ++xx)
                s = fmaf(row[xx], T.cm[u][xx], s);          // FFMA-imm
            // y-DCT accumulate; cm[a][0]==1 -> y==0 is pure init
            if (y == 0) {
#pragma unroll
                for (int a = 0; a < 8; ++a)
                    coef[a][u] = s * T.cm[a][0];            // cm[a][0]==1 -> MOV
            } else {
#pragma unroll
                for (int a = 0; a < 8; ++a)
                    coef[a][u] = fmaf(s, T.cm[a][y], coef[a][u]);  // FFMA-imm
            }
        }
    }

#pragma unroll
    for (int a = 0; a < 8; ++a)
#pragma unroll
        for (int u = 0; u < 8; ++u)
            dst[(long)T.ch[a][u] << 12] = coef[a][u] * T.scl[LC][a][u];  // FMUL-imm
}

__global__ void __launch_bounds__(128, 6)
dct_kernel(const float* __restrict__ x, float* __restrict__ out) {
    const long gid = (long)blockIdx.x * 128 + threadIdx.x;
    const int  wb  = (int)(gid & 63);
    const int  hb  = (int)((gid >> 6) & 63);
    const int  bc  = (int)(gid >> 12);           // b*3 + c
    const int  c   = bc % 3;                     // uniform within CTA

    const float* src = x + (((long)bc * 512 + hb * 8) * 512 + wb * 8);
    float*       dst = out + ((long)bc << 18) + (hb << 6) + wb;

    if (c == 0) dct_body<0>(src, dst);
    else        dct_body<1>(src, dst);
}

extern "C" void kernel_launch(void* const* d_in, const int* in_sizes, int n_in,
                              void* d_out, int out_size) {
    const float* x   = (const float*)d_in[0];
    float*       out = (float*)d_out;
    // 32*3*64*64 = 393216 blocks, 128 threads (blocks) per CTA -> 3072 CTAs
    dct_kernel<<<3072, 128>>>(x, out);
}

// round 9
// speedup vs baseline: 1.0685x; 1.0685x over previous
#include <cuda_runtime.h>

// DCT compression: per 8x8 block 2D DCT (cos basis with PI=3.1415), diagonal
// norm, zigzag channel scatter, 1/Q quant scale. Single fused kernel.
//
// R9 = R7 (best: front-batched loads + constexpr FFMA-immediate tables,
// no smem) with one delta: the 16 LDG.128 become 8 plain LDG.256
// (ld.global.nc.v4.b64, NO cache hints - hints were the R5 regression,
// not the width). Halves load instruction issue; same bytes/wavefronts.
//
// Input : x (32, 3, 512, 512) f32
// Output: (32, 192, 64, 64) f32, out[b, c*64 + z(a,u), hb, wb]

typedef unsigned long long ull;

// ---- constexpr math (compile-time only) ----
__host__ __device__ constexpr double cc_cos(double x) {
    const double TWO_PI = 6.283185307179586476925286766559;
    const double PI_D   = 3.14159265358979323846;
    while (x >  PI_D) x -= TWO_PI;
    while (x < -PI_D) x += TWO_PI;
    double x2 = x * x, t = 1.0, s = 1.0;
    for (int n = 1; n <= 16; ++n) { t *= -x2 / ((2.0 * n - 1.0) * (2.0 * n)); s += t; }
    return s;
}

// Mirrors the module: arg = f32((f+0.5)*3.1415f) * f32(j*0.125f), cos of that.
__host__ __device__ constexpr float cc_cm(int f, int j) {
    float ap = (float)(f + 0.5f) * 3.1415f;
    float bj = (float)j * 0.125f;
    return (float)cc_cos((double)(ap * bj));
}

// Module's zigzag() p[y][x], closed form.
__host__ __device__ constexpr int zz_p(int y, int x) {
    int s = x + y;
    if (s < 8) {
        int t = (s + 1) * (s + 2) / 2;
        return (s & 1) ? (t - y - 1) : (t - x - 1);
    }
    int yy = 7 - y, xx = 7 - x;
    int s2 = xx + yy;
    int t = (s2 + 1) * (s2 + 2) / 2;
    return 63 - ((s2 & 1) ? (t - yy - 1) : (t - xx - 1));
}

struct Tabs {
    float cm[8][8];     // cos basis
    float scl[2][8][8]; // [luma?0:1][a][u] = norm(a,u)/Q[ch]
    int   ch[8][8];     // zigzag channel for (a,u)
};

__host__ __device__ constexpr Tabs make_tabs() {
    constexpr float TLQ[64] = {
        16,11,10,16,24,40,51,61, 12,12,14,19,26,58,60,55,
        14,13,16,24,40,57,69,56, 14,17,22,29,51,87,80,62,
        18,22,37,56,68,109,103,77, 24,35,55,64,81,104,113,92,
        49,64,78,87,103,121,120,101, 72,92,95,98,112,100,103,99};
    constexpr float CQQ[64] = {
        17,18,24,47,99,99,99,99, 18,21,26,66,99,99,99,99,
        24,26,56,99,99,99,99,99, 47,66,99,99,99,99,99,99,
        99,99,99,99,99,99,99,99, 99,99,99,99,99,99,99,99,
        99,99,99,99,99,99,99,99, 99,99,99,99,99,99,99,99};
    Tabs t{};
    for (int f = 0; f < 8; ++f)
        for (int j = 0; j < 8; ++j)
            t.cm[f][j] = cc_cm(f, j);
    for (int a = 0; a < 8; ++a)
        for (int u = 0; u < 8; ++u) {
            int ch = zz_p(u, a);                // z = pattern.T
            t.ch[a][u] = ch;
            float nrm = ((a == 0) || (u == 0)) ? 0.17677669529663687f : 0.25f;
            t.scl[0][a][u] = nrm / TLQ[ch];
            t.scl[1][a][u] = nrm / CQQ[ch];
        }
    return t;
}

// One 256-bit load = one full 8-float block row (plain, no cache hints).
__device__ __forceinline__ void ldg256(const float* p, float* r8) {
    ull a, b, c, d;
    asm volatile("ld.global.nc.v4.b64 {%0,%1,%2,%3}, [%4];"
                 : "=l"(a), "=l"(b), "=l"(c), "=l"(d) : "l"(p));
    asm("mov.b64 {%0, %1}, %2;" : "=f"(r8[0]), "=f"(r8[1]) : "l"(a));
    asm("mov.b64 {%0, %1}, %2;" : "=f"(r8[2]), "=f"(r8[3]) : "l"(b));
    asm("mov.b64 {%0, %1}, %2;" : "=f"(r8[4]), "=f"(r8[5]) : "l"(c));
    asm("mov.b64 {%0, %1}, %2;" : "=f"(r8[6]), "=f"(r8[7]) : "l"(d));
}

template<int LC>
__device__ __forceinline__ void dct_body(const float* __restrict__ src,
                                         float* __restrict__ dst) {
    constexpr Tabs T = make_tabs();   // fully folded to immediates

    // Front-batch the full 8x8 block: 8 LDG.256 in flight
    float blk[8][8];
#pragma unroll
    for (int y = 0; y < 8; ++y)
        ldg256(src + y * 512, blk[y]);

#pragma unroll
    for (int a = 0; a < 8; ++a) {
        float tmp[8];
#pragma unroll
        for (int xx = 0; xx < 8; ++xx) {
            float acc = blk[0][xx] * T.cm[a][0];   // cm[a][0]==1 -> folds
#pragma unroll
            for (int y = 1; y < 8; ++y)
                acc = fmaf(blk[y][xx], T.cm[a][y], acc);   // FFMA-imm
            tmp[xx] = acc;
        }
#pragma unroll
        for (int u = 0; u < 8; ++u) {
            float s = tmp[0] * T.cm[u][0];          // ==tmp[0]
#pragma unroll
            for (int xx = 1; xx < 8; ++xx)
                s = fmaf(tmp[xx], T.cm[u][xx], s);  // FFMA-imm
            dst[T.ch[a][u] << 12] = s * T.scl[LC][a][u];  // FMUL-imm + STG imm-offset
        }
    }
}

__global__ void __launch_bounds__(128, 5)
dct_kernel(const float* __restrict__ x, float* __restrict__ out) {
    const unsigned gid = blockIdx.x * 128u + threadIdx.x;
    const int  wb  = (int)(gid & 63);
    const int  hb  = (int)((gid >> 6) & 63);
    const int  bc  = (int)(gid >> 12);           // b*3 + c
    const int  c   = bc % 3;                     // uniform within CTA

    const float* src = x + ((unsigned)bc * 512u + hb * 8u) * 512u + wb * 8u;
    float*       dst = out + ((unsigned)bc << 18) + (hb << 6) + wb;

    if (c == 0) dct_body<0>(src, dst);
    else        dct_body<1>(src, dst);
}

extern "C" void kernel_launch(void* const* d_in, const int* in_sizes, int n_in,
                              void* d_out, int out_size) {
    const float* x   = (const float*)d_in[0];
    float*       out = (float*)d_out;
    // 32*3*64*64 = 393216 blocks, 128 threads (blocks) per CTA -> 3072 CTAs
    dct_kernel<<<3072, 128>>>(x, out);
}

// round 10
// speedup vs baseline: 1.1170x; 1.0453x over previous
#include <cuda_runtime.h>

// DCT compression: per 8x8 block 2D DCT (cos basis with PI=3.1415), diagonal
// norm, zigzag channel scatter, 1/Q quant scale. Single fused kernel.
//
// R10 = R7 (best: 16x LDG.128 front-batch + constexpr FFMA-immediate tables,
// no smem) with ONE delta: stores use st.global.cs (evict-first) so the
// 100MB output stream does not evict the input from L2 between graph
// replays. Loads untouched (R5 showed evict_last on loads thrashes; R9
// showed LDG.256 loses request parallelism).
//
// Input : x (32, 3, 512, 512) f32
// Output: (32, 192, 64, 64) f32, out[b, c*64 + z(a,u), hb, wb]

// ---- constexpr math (compile-time only) ----
__host__ __device__ constexpr double cc_cos(double x) {
    const double TWO_PI = 6.283185307179586476925286766559;
    const double PI_D   = 3.14159265358979323846;
    while (x >  PI_D) x -= TWO_PI;
    while (x < -PI_D) x += TWO_PI;
    double x2 = x * x, t = 1.0, s = 1.0;
    for (int n = 1; n <= 16; ++n) { t *= -x2 / ((2.0 * n - 1.0) * (2.0 * n)); s += t; }
    return s;
}

// Mirrors the module: arg = f32((f+0.5)*3.1415f) * f32(j*0.125f), cos of that.
__host__ __device__ constexpr float cc_cm(int f, int j) {
    float ap = (float)(f + 0.5f) * 3.1415f;
    float bj = (float)j * 0.125f;
    return (float)cc_cos((double)(ap * bj));
}

// Module's zigzag() p[y][x], closed form.
__host__ __device__ constexpr int zz_p(int y, int x) {
    int s = x + y;
    if (s < 8) {
        int t = (s + 1) * (s + 2) / 2;
        return (s & 1) ? (t - y - 1) : (t - x - 1);
    }
    int yy = 7 - y, xx = 7 - x;
    int s2 = xx + yy;
    int t = (s2 + 1) * (s2 + 2) / 2;
    return 63 - ((s2 & 1) ? (t - yy - 1) : (t - xx - 1));
}

struct Tabs {
    float cm[8][8];     // cos basis
    float scl[2][8][8]; // [luma?0:1][a][u] = norm(a,u)/Q[ch]
    int   ch[8][8];     // zigzag channel for (a,u)
};

__host__ __device__ constexpr Tabs make_tabs() {
    constexpr float TLQ[64] = {
        16,11,10,16,24,40,51,61, 12,12,14,19,26,58,60,55,
        14,13,16,24,40,57,69,56, 14,17,22,29,51,87,80,62,
        18,22,37,56,68,109,103,77, 24,35,55,64,81,104,113,92,
        49,64,78,87,103,121,120,101, 72,92,95,98,112,100,103,99};
    constexpr float CQQ[64] = {
        17,18,24,47,99,99,99,99, 18,21,26,66,99,99,99,99,
        24,26,56,99,99,99,99,99, 47,66,99,99,99,99,99,99,
        99,99,99,99,99,99,99,99, 99,99,99,99,99,99,99,99,
        99,99,99,99,99,99,99,99, 99,99,99,99,99,99,99,99};
    Tabs t{};
    for (int f = 0; f < 8; ++f)
        for (int j = 0; j < 8; ++j)
            t.cm[f][j] = cc_cm(f, j);
    for (int a = 0; a < 8; ++a)
        for (int u = 0; u < 8; ++u) {
            int ch = zz_p(u, a);                // z = pattern.T
            t.ch[a][u] = ch;
            float nrm = ((a == 0) || (u == 0)) ? 0.17677669529663687f : 0.25f;
            t.scl[0][a][u] = nrm / TLQ[ch];
            t.scl[1][a][u] = nrm / CQQ[ch];
        }
    return t;
}

__device__ __forceinline__ void stg_cs(float* p, float v) {
    asm volatile("st.global.cs.f32 [%0], %1;" :: "l"(p), "f"(v) : "memory");
}

template<int LC>
__device__ __forceinline__ void dct_body(const float* __restrict__ src,
                                         float* __restrict__ dst) {
    constexpr Tabs T = make_tabs();   // fully folded to immediates

    // Front-batch the full 8x8 block (16 LDG.128 in flight)
    float blk[8][8];
#pragma unroll
    for (int y = 0; y < 8; ++y) {
        float4 p0 = __ldg((const float4*)(src + (long)y * 512));
        float4 p1 = __ldg((const float4*)(src + (long)y * 512 + 4));
        blk[y][0] = p0.x; blk[y][1] = p0.y; blk[y][2] = p0.z; blk[y][3] = p0.w;
        blk[y][4] = p1.x; blk[y][5] = p1.y; blk[y][6] = p1.z; blk[y][7] = p1.w;
    }

#pragma unroll
    for (int a = 0; a < 8; ++a) {
        float tmp[8];
#pragma unroll
        for (int xx = 0; xx < 8; ++xx) {
            float acc = blk[0][xx] * T.cm[a][0];   // cm[a][0]==1 -> folds
#pragma unroll
            for (int y = 1; y < 8; ++y)
                acc = fmaf(blk[y][xx], T.cm[a][y], acc);   // FFMA-imm
            tmp[xx] = acc;
        }
#pragma unroll
        for (int u = 0; u < 8; ++u) {
            float s = tmp[0] * T.cm[u][0];          // ==tmp[0]
#pragma unroll
            for (int xx = 1; xx < 8; ++xx)
                s = fmaf(tmp[xx], T.cm[u][xx], s);  // FFMA-imm
            stg_cs(dst + ((long)T.ch[a][u] << 12), s * T.scl[LC][a][u]);
        }
    }
}

__global__ void __launch_bounds__(128, 5)
dct_kernel(const float* __restrict__ x, float* __restrict__ out) {
    const long gid = (long)blockIdx.x * 128 + threadIdx.x;
    const int  wb  = (int)(gid & 63);
    const int  hb  = (int)((gid >> 6) & 63);
    const int  bc  = (int)(gid >> 12);           // b*3 + c
    const int  c   = bc % 3;                     // uniform within CTA

    const float* src = x + (((long)bc * 512 + hb * 8) * 512 + wb * 8);
    float*       dst = out + ((long)bc << 18) + (hb << 6) + wb;

    if (c == 0) dct_body<0>(src, dst);
    else        dct_body<1>(src, dst);
}

extern "C" void kernel_launch(void* const* d_in, const int* in_sizes, int n_in,
                              void* d_out, int out_size) {
    const float* x   = (const float*)d_in[0];
    float*       out = (float*)d_out;
    // 32*3*64*64 = 393216 blocks, 128 threads (blocks) per CTA -> 3072 CTAs
    dct_kernel<<<3072, 128>>>(x, out);
}

// round 11
// speedup vs baseline: 1.1180x; 1.0009x over previous
#include <cuda_runtime.h>

// DCT compression: per 8x8 block 2D DCT (cos basis with PI=3.1415), diagonal
// norm, zigzag channel scatter, 1/Q quant scale. Single fused kernel.
//
// R11 = R10 (best structure: 16x LDG.128 front-batch + constexpr
// FFMA-immediate tables, no smem, .cs stores) with occupancy forced to
// 6 CTAs/SM via __launch_bounds__(128,6) (reg cap 85) and 32-bit index
// math to help ptxas fit. Structure untouched - every structural change
// (R2 smem, R8 streaming, R9 LDG.256, R4/5 load hints) regressed.
//
// Input : x (32, 3, 512, 512) f32
// Output: (32, 192, 64, 64) f32, out[b, c*64 + z(a,u), hb, wb]

// ---- constexpr math (compile-time only) ----
__host__ __device__ constexpr double cc_cos(double x) {
    const double TWO_PI = 6.283185307179586476925286766559;
    const double PI_D   = 3.14159265358979323846;
    while (x >  PI_D) x -= TWO_PI;
    while (x < -PI_D) x += TWO_PI;
    double x2 = x * x, t = 1.0, s = 1.0;
    for (int n = 1; n <= 16; ++n) { t *= -x2 / ((2.0 * n - 1.0) * (2.0 * n)); s += t; }
    return s;
}

// Mirrors the module: arg = f32((f+0.5)*3.1415f) * f32(j*0.125f), cos of that.
__host__ __device__ constexpr float cc_cm(int f, int j) {
    float ap = (float)(f + 0.5f) * 3.1415f;
    float bj = (float)j * 0.125f;
    return (float)cc_cos((double)(ap * bj));
}

// Module's zigzag() p[y][x], closed form.
__host__ __device__ constexpr int zz_p(int y, int x) {
    int s = x + y;
    if (s < 8) {
        int t = (s + 1) * (s + 2) / 2;
        return (s & 1) ? (t - y - 1) : (t - x - 1);
    }
    int yy = 7 - y, xx = 7 - x;
    int s2 = xx + yy;
    int t = (s2 + 1) * (s2 + 2) / 2;
    return 63 - ((s2 & 1) ? (t - yy - 1) : (t - xx - 1));
}

struct Tabs {
    float cm[8][8];     // cos basis
    float scl[2][8][8]; // [luma?0:1][a][u] = norm(a,u)/Q[ch]
    int   ch[8][8];     // zigzag channel for (a,u)
};

__host__ __device__ constexpr Tabs make_tabs() {
    constexpr float TLQ[64] = {
        16,11,10,16,24,40,51,61, 12,12,14,19,26,58,60,55,
        14,13,16,24,40,57,69,56, 14,17,22,29,51,87,80,62,
        18,22,37,56,68,109,103,77, 24,35,55,64,81,104,113,92,
        49,64,78,87,103,121,120,101, 72,92,95,98,112,100,103,99};
    constexpr float CQQ[64] = {
        17,18,24,47,99,99,99,99, 18,21,26,66,99,99,99,99,
        24,26,56,99,99,99,99,99, 47,66,99,99,99,99,99,99,
        99,99,99,99,99,99,99,99, 99,99,99,99,99,99,99,99,
        99,99,99,99,99,99,99,99, 99,99,99,99,99,99,99,99};
    Tabs t{};
    for (int f = 0; f < 8; ++f)
        for (int j = 0; j < 8; ++j)
            t.cm[f][j] = cc_cm(f, j);
    for (int a = 0; a < 8; ++a)
        for (int u = 0; u < 8; ++u) {
            int ch = zz_p(u, a);                // z = pattern.T
            t.ch[a][u] = ch;
            float nrm = ((a == 0) || (u == 0)) ? 0.17677669529663687f : 0.25f;
            t.scl[0][a][u] = nrm / TLQ[ch];
            t.scl[1][a][u] = nrm / CQQ[ch];
        }
    return t;
}

__device__ __forceinline__ void stg_cs(float* p, float v) {
    asm volatile("st.global.cs.f32 [%0], %1;" :: "l"(p), "f"(v) : "memory");
}

template<int LC>
__device__ __forceinline__ void dct_body(const float* __restrict__ src,
                                         float* __restrict__ dst) {
    constexpr Tabs T = make_tabs();   // fully folded to immediates

    // Front-batch the full 8x8 block (16 LDG.128 in flight)
    float blk[8][8];
#pragma unroll
    for (int y = 0; y < 8; ++y) {
        float4 p0 = __ldg((const float4*)(src + y * 512u));
        float4 p1 = __ldg((const float4*)(src + y * 512u + 4u));
        blk[y][0] = p0.x; blk[y][1] = p0.y; blk[y][2] = p0.z; blk[y][3] = p0.w;
        blk[y][4] = p1.x; blk[y][5] = p1.y; blk[y][6] = p1.z; blk[y][7] = p1.w;
    }

#pragma unroll
    for (int a = 0; a < 8; ++a) {
        float tmp[8];
#pragma unroll
        for (int xx = 0; xx < 8; ++xx) {
            float acc = blk[0][xx] * T.cm[a][0];   // cm[a][0]==1 -> folds
#pragma unroll
            for (int y = 1; y < 8; ++y)
                acc = fmaf(blk[y][xx], T.cm[a][y], acc);   // FFMA-imm
            tmp[xx] = acc;
        }
#pragma unroll
        for (int u = 0; u < 8; ++u) {
            float s = tmp[0] * T.cm[u][0];          // ==tmp[0]
#pragma unroll
            for (int xx = 1; xx < 8; ++xx)
                s = fmaf(tmp[xx], T.cm[u][xx], s);  // FFMA-imm
            stg_cs(dst + (T.ch[a][u] << 12), s * T.scl[LC][a][u]);  // imm-scaled offset
        }
    }
}

__global__ void __launch_bounds__(128, 6)
dct_kernel(const float* __restrict__ x, float* __restrict__ out) {
    const unsigned gid = blockIdx.x * 128u + threadIdx.x;   // < 2^19, 32-bit safe
    const unsigned wb  = gid & 63u;
    const unsigned hb  = (gid >> 6) & 63u;
    const unsigned bc  = gid >> 12;              // b*3 + c, < 96
    const unsigned c   = bc % 3u;                // uniform within CTA

    const float* src = x + (bc * 512u + hb * 8u) * 512u + wb * 8u;   // < 2^25 elems
    float*       dst = out + (bc << 18) + (hb << 6) + wb;

    if (c == 0) dct_body<0>(src, dst);
    else        dct_body<1>(src, dst);
}

extern "C" void kernel_launch(void* const* d_in, const int* in_sizes, int n_in,
                              void* d_out, int out_size) {
    const float* x   = (const float*)d_in[0];
    float*       out = (float*)d_out;
    // 32*3*64*64 = 393216 blocks, 128 threads (blocks) per CTA -> 3072 CTAs
    dct_kernel<<<3072, 128>>>(x, out);
}